// round 15
// baseline (speedup 1.0000x reference)
#include <cuda_runtime.h>

#define N_NODES 100000
#define E_EDGES 1600000
#define IN_C    128
#define H_C     64
#define OUT_C   32
#define NBLK    391          // ceil(N_NODES/256)

// ---------------- scratch (device-side access only!) ----------------
__device__ __align__(16) float g_dinv[N_NODES];
__device__ int   g_degi    [N_NODES];
__device__ int   g_cursor  [N_NODES];
__device__ int   g_scani   [N_NODES];
__device__ int   g_rowstart[N_NODES];
__device__ int   g_bsum    [NBLK];
__device__ int   g_csr_src [E_EDGES];
__device__ __align__(16) float g_t1  [N_NODES * H_C];
__device__ __align__(16) float g_agg1[N_NODES * H_C];   // relu already applied
__device__ __align__(16) float g_t2  [N_NODES * H_C];

// ---------------- packed f32x2 helpers ----------------
__device__ __forceinline__ unsigned long long pack2(float x) {
    unsigned long long r;
    asm("mov.b64 %0, {%1, %1};" : "=l"(r) : "f"(x));
    return r;
}
__device__ __forceinline__ void fma2(unsigned long long& d,
                                     unsigned long long a,
                                     unsigned long long b) {
    asm("fma.rn.f32x2 %0, %1, %2, %0;" : "+l"(d) : "l"(a), "l"(b));
}

// ---------------- degree / CSR build ----------------
__global__ void k_init() {
    int n = blockIdx.x * blockDim.x + threadIdx.x;
    if (n < N_NODES) g_degi[n] = 0;
}

__global__ void k_degcnt(const int* __restrict__ ei) {
    int e = blockIdx.x * blockDim.x + threadIdx.x;
    if (e < E_EDGES) atomicAdd(&g_degi[ei[E_EDGES + e]], 1);
}

// block-local inclusive scan of degrees (256/block)
__global__ void k_scan_block() {
    __shared__ int sh[256];
    int tid = threadIdx.x;
    int i = blockIdx.x * 256 + tid;
    int v = (i < N_NODES) ? g_degi[i] : 0;
    sh[tid] = v;
    __syncthreads();
#pragma unroll
    for (int off = 1; off < 256; off <<= 1) {
        int t = (tid >= off) ? sh[tid - off] : 0;
        __syncthreads();
        sh[tid] += t;
        __syncthreads();
    }
    if (i < N_NODES) g_scani[i] = sh[tid];
    if (tid == 255) g_bsum[blockIdx.x] = sh[255];
}

// fused: per-block top-prefix reduction + rowstart + dinv + cursor zero
__global__ void k_scan_add() {
    __shared__ int sh[256];
    int tid = threadIdx.x;
    // sum of bsum[0 .. blockIdx.x-1]
    int acc = 0;
    for (int j = tid; j < blockIdx.x; j += 256) acc += g_bsum[j];
    sh[tid] = acc;
    __syncthreads();
#pragma unroll
    for (int off = 128; off > 0; off >>= 1) {
        if (tid < off) sh[tid] += sh[tid + off];
        __syncthreads();
    }
    int binc = sh[0];

    int i = blockIdx.x * 256 + tid;
    if (i < N_NODES) {
        int dg = g_degi[i];
        g_rowstart[i] = g_scani[i] - dg + binc;   // exclusive prefix
        g_dinv[i] = rsqrtf((float)dg + 1.0f);
        g_cursor[i] = 0;
    }
}

__global__ void k_fill(const int* __restrict__ ei) {
    int e = blockIdx.x * blockDim.x + threadIdx.x;
    if (e < E_EDGES) {
        int s = ei[e];
        int d = ei[E_EDGES + e];
        int pos = g_rowstart[d] + atomicAdd(&g_cursor[d], 1);
        g_csr_src[pos] = s;
    }
}

// ---------------- matmul 1: t1 = x @ W1  (4 nodes x 16 ch per thread, f32x2) ----------
__global__ __launch_bounds__(256) void k_mm1(const float* __restrict__ x,
                                             const float* __restrict__ W1) {
    __shared__ float Ws[IN_C * H_C];   // 32 KB
    for (int i = threadIdx.x; i < IN_C * H_C; i += 256) Ws[i] = W1[i];
    __syncthreads();

    int tid  = threadIdx.x;
    int quad = blockIdx.x * 64 + (tid >> 2);
    int nb   = quad * 4;
    if (nb >= N_NODES) return;
    int cb = (tid & 3) << 4;   // 16-channel group

    unsigned long long acc[4][8];
#pragma unroll
    for (int j = 0; j < 4; j++)
#pragma unroll
        for (int q = 0; q < 8; q++) acc[j][q] = 0ull;

    const float* xb = x + (size_t)nb * IN_C;
    for (int k4 = 0; k4 < IN_C / 4; k4++) {
        float4 xv[4];
#pragma unroll
        for (int j = 0; j < 4; j++)
            xv[j] = (nb + j < N_NODES)
                  ? *(const float4*)(xb + (size_t)j * IN_C + k4 * 4)
                  : make_float4(0.f, 0.f, 0.f, 0.f);
#pragma unroll
        for (int kk = 0; kk < 4; kk++) {
            const ulonglong2* wr = (const ulonglong2*)(&Ws[(k4 * 4 + kk) * H_C + cb]);
            ulonglong2 wv0 = wr[0], wv1 = wr[1], wv2 = wr[2], wv3 = wr[3];
            unsigned long long w[8] = {wv0.x, wv0.y, wv1.x, wv1.y,
                                       wv2.x, wv2.y, wv3.x, wv3.y};
#pragma unroll
            for (int j = 0; j < 4; j++) {
                float xs = (kk == 0) ? xv[j].x : (kk == 1) ? xv[j].y
                         : (kk == 2) ? xv[j].z : xv[j].w;
                unsigned long long xp = pack2(xs);
#pragma unroll
                for (int q = 0; q < 8; q++) fma2(acc[j][q], xp, w[q]);
            }
        }
    }

#pragma unroll
    for (int j = 0; j < 4; j++) {
        if (nb + j < N_NODES) {
            ulonglong2* o = (ulonglong2*)(g_t1 + (size_t)(nb + j) * H_C + cb);
#pragma unroll
            for (int q = 0; q < 4; q++) {
                ulonglong2 v; v.x = acc[j][2*q]; v.y = acc[j][2*q+1];
                o[q] = v;
            }
        }
    }
}

// ---------------- gather ----------------
// result[n] = dinv[n]*sum_s dinv[s]*t[s] + t[n]*dinv[n]^2 + bias
// layer 0: t = g_t1, write relu(result) to g_agg1
// layer 1: t = g_t2, write split [mu ; logstd] directly to out
// 2 nodes per warp (16 lanes each); float4 (4 channels) per lane; 4-edge pipeline
__global__ __launch_bounds__(256) void k_gather(int layer,
                                                const float* __restrict__ bA,
                                                const float* __restrict__ bB,
                                                float* __restrict__ outp) {
    int warp = (blockIdx.x * 256 + threadIdx.x) >> 5;
    int lane = threadIdx.x & 31;
    int half = lane >> 4;               // 0 or 1
    int n = warp * 2 + half;
    if (n >= N_NODES) return;
    int c = (lane & 15) << 2;           // 4-channel group: 0..60

    const float* t = layer ? g_t2 : g_t1;

    int rs = g_rowstart[n];
    int dg = g_degi[n];
    float dd = g_dinv[n];

    float4 A = make_float4(0.f, 0.f, 0.f, 0.f);
    float4 B = A, C = A, D = A;

    int i = 0;
    for (; i + 4 <= dg; i += 4) {
        int s0 = g_csr_src[rs + i];
        int s1 = g_csr_src[rs + i + 1];
        int s2 = g_csr_src[rs + i + 2];
        int s3 = g_csr_src[rs + i + 3];
        float e0 = g_dinv[s0], e1 = g_dinv[s1];
        float e2 = g_dinv[s2], e3 = g_dinv[s3];
        float4 v0 = *(const float4*)(t + (size_t)s0 * H_C + c);
        float4 v1 = *(const float4*)(t + (size_t)s1 * H_C + c);
        float4 v2 = *(const float4*)(t + (size_t)s2 * H_C + c);
        float4 v3 = *(const float4*)(t + (size_t)s3 * H_C + c);
        A.x += e0 * v0.x; A.y += e0 * v0.y; A.z += e0 * v0.z; A.w += e0 * v0.w;
        B.x += e1 * v1.x; B.y += e1 * v1.y; B.z += e1 * v1.z; B.w += e1 * v1.w;
        C.x += e2 * v2.x; C.y += e2 * v2.y; C.z += e2 * v2.z; C.w += e2 * v2.w;
        D.x += e3 * v3.x; D.y += e3 * v3.y; D.z += e3 * v3.z; D.w += e3 * v3.w;
    }
    for (; i < dg; i++) {
        int s = g_csr_src[rs + i];
        float ds = g_dinv[s];
        float4 v = *(const float4*)(t + (size_t)s * H_C + c);
        A.x += ds * v.x; A.y += ds * v.y; A.z += ds * v.z; A.w += ds * v.w;
    }
    float r0 = ((A.x + B.x) + (C.x + D.x)) * dd;
    float r1 = ((A.y + B.y) + (C.y + D.y)) * dd;
    float r2 = ((A.z + B.z) + (C.z + D.z)) * dd;
    float r3 = ((A.w + B.w) + (C.w + D.w)) * dd;

    float4 self = *(const float4*)(t + (size_t)n * H_C + c);
    float4 bias = (c < 32) ? *(const float4*)(bA + c)
                           : *(const float4*)(bB + (c - 32));
    float d2 = dd * dd;
    r0 += self.x * d2 + bias.x;
    r1 += self.y * d2 + bias.y;
    r2 += self.z * d2 + bias.z;
    r3 += self.w * d2 + bias.w;

    if (layer == 0) {
        *(float4*)(g_agg1 + (size_t)n * H_C + c) =
            make_float4(fmaxf(r0, 0.f), fmaxf(r1, 0.f),
                        fmaxf(r2, 0.f), fmaxf(r3, 0.f));
    } else {
        size_t idx = (c < 32)
            ? (size_t)n * OUT_C + c
            : (size_t)N_NODES * OUT_C + (size_t)n * OUT_C + (c - 32);
        *(float4*)(outp + idx) = make_float4(r0, r1, r2, r3);
    }
}

// ---------------- matmul 2: t2 = agg1 @ [W_mu|W_logstd]  (agg1 already relu'd) --------
__global__ __launch_bounds__(256) void k_mm2(const float* __restrict__ Wmu,
                                             const float* __restrict__ Wls) {
    __shared__ float Ws[H_C * H_C];   // 16 KB, columns = [W_mu | W_logstd]
    for (int i = threadIdx.x; i < H_C * H_C; i += 256) {
        int k = i >> 6;
        int j = i & 63;
        Ws[i] = (j < OUT_C) ? Wmu[k * OUT_C + j] : Wls[k * OUT_C + (j - OUT_C)];
    }
    __syncthreads();

    int tid  = threadIdx.x;
    int quad = blockIdx.x * 64 + (tid >> 2);
    int nb   = quad * 4;
    if (nb >= N_NODES) return;
    int cb = (tid & 3) << 4;

    unsigned long long acc[4][8];
#pragma unroll
    for (int j = 0; j < 4; j++)
#pragma unroll
        for (int q = 0; q < 8; q++) acc[j][q] = 0ull;

    const float* hb = g_agg1 + (size_t)nb * H_C;
    for (int k4 = 0; k4 < H_C / 4; k4++) {
        float4 xv[4];
#pragma unroll
        for (int j = 0; j < 4; j++)
            xv[j] = (nb + j < N_NODES)
                  ? *(const float4*)(hb + (size_t)j * H_C + k4 * 4)
                  : make_float4(0.f, 0.f, 0.f, 0.f);
#pragma unroll
        for (int kk = 0; kk < 4; kk++) {
            const ulonglong2* wr = (const ulonglong2*)(&Ws[(k4 * 4 + kk) * H_C + cb]);
            ulonglong2 wv0 = wr[0], wv1 = wr[1], wv2 = wr[2], wv3 = wr[3];
            unsigned long long w[8] = {wv0.x, wv0.y, wv1.x, wv1.y,
                                       wv2.x, wv2.y, wv3.x, wv3.y};
#pragma unroll
            for (int j = 0; j < 4; j++) {
                float xs = (kk == 0) ? xv[j].x : (kk == 1) ? xv[j].y
                         : (kk == 2) ? xv[j].z : xv[j].w;
                unsigned long long xp = pack2(xs);
#pragma unroll
                for (int q = 0; q < 8; q++) fma2(acc[j][q], xp, w[q]);
            }
        }
    }

#pragma unroll
    for (int j = 0; j < 4; j++) {
        if (nb + j < N_NODES) {
            ulonglong2* o = (ulonglong2*)(g_t2 + (size_t)(nb + j) * H_C + cb);
#pragma unroll
            for (int q = 0; q < 4; q++) {
                ulonglong2 v; v.x = acc[j][2*q]; v.y = acc[j][2*q+1];
                o[q] = v;
            }
        }
    }
}

// ---------------- launch ----------------
extern "C" void kernel_launch(void* const* d_in, const int* in_sizes, int n_in,
                              void* d_out, int out_size) {
    const float* x   = (const float*)d_in[0];
    const int*   ei  = (const int*)  d_in[1];
    const float* W1  = (const float*)d_in[2];
    const float* b1  = (const float*)d_in[3];
    const float* Wmu = (const float*)d_in[4];
    const float* bmu = (const float*)d_in[5];
    const float* Wls = (const float*)d_in[6];
    const float* bls = (const float*)d_in[7];
    float* out = (float*)d_out;

    const int TB = 256;
    const int EB = (E_EDGES + TB - 1) / TB;   // 6250

    k_init      <<<NBLK, TB>>>();
    k_degcnt    <<<EB,   TB>>>(ei);
    k_scan_block<<<NBLK, TB>>>();
    k_scan_add  <<<NBLK, TB>>>();
    k_fill      <<<EB,   TB>>>(ei);

    k_mm1<<<NBLK, TB>>>(x, W1);

    int gwarps  = (N_NODES + 1) / 2;                   // 2 nodes per warp
    int gblocks = (gwarps * 32 + TB - 1) / TB;         // 6250
    k_gather<<<gblocks, TB>>>(0, b1, b1 + 32, nullptr);

    k_mm2<<<NBLK, TB>>>(Wmu, Wls);

    k_gather<<<gblocks, TB>>>(1, bmu, bls, out);
}

// round 16
// speedup vs baseline: 1.0823x; 1.0823x over previous
#include <cuda_runtime.h>

#define N_NODES 100000
#define E_EDGES 1600000
#define IN_C    128
#define H_C     64
#define OUT_C   32
#define NBLK    391          // ceil(N_NODES/256)

// ---------------- scratch (device-side access only!) ----------------
__device__ __align__(16) float g_dinv[N_NODES];
__device__ int   g_degi    [N_NODES];
__device__ int   g_cursor  [N_NODES];
__device__ int   g_scani   [N_NODES];
__device__ int   g_rowstart[N_NODES];
__device__ int   g_bsum    [NBLK];
__device__ int   g_csr_src [E_EDGES];
__device__ __align__(16) float g_t1  [N_NODES * H_C];   // dinv-prescaled x@W1
__device__ __align__(16) float g_agg1[N_NODES * H_C];   // relu'd layer-1 output
__device__ __align__(16) float g_t2  [N_NODES * H_C];   // dinv-prescaled h@[Wmu|Wls]

// ---------------- packed f32x2 helpers ----------------
__device__ __forceinline__ unsigned long long pack2(float x) {
    unsigned long long r;
    asm("mov.b64 %0, {%1, %1};" : "=l"(r) : "f"(x));
    return r;
}
__device__ __forceinline__ void fma2(unsigned long long& d,
                                     unsigned long long a,
                                     unsigned long long b) {
    asm("fma.rn.f32x2 %0, %1, %2, %0;" : "+l"(d) : "l"(a), "l"(b));
}
__device__ __forceinline__ void add2(unsigned long long& d,
                                     unsigned long long v) {
    asm("add.rn.f32x2 %0, %0, %1;" : "+l"(d) : "l"(v));
}
__device__ __forceinline__ void mul2(unsigned long long& d,
                                     unsigned long long v) {
    asm("mul.rn.f32x2 %0, %0, %1;" : "+l"(d) : "l"(v));
}

// ---------------- degree / CSR build ----------------
__global__ void k_init() {
    int n = blockIdx.x * blockDim.x + threadIdx.x;
    if (n < N_NODES) g_degi[n] = 0;
}

__global__ void k_degcnt(const int* __restrict__ ei) {
    int e = blockIdx.x * blockDim.x + threadIdx.x;
    if (e < E_EDGES) atomicAdd(&g_degi[ei[E_EDGES + e]], 1);
}

// block-local inclusive scan of degrees (256/block)
__global__ void k_scan_block() {
    __shared__ int sh[256];
    int tid = threadIdx.x;
    int i = blockIdx.x * 256 + tid;
    int v = (i < N_NODES) ? g_degi[i] : 0;
    sh[tid] = v;
    __syncthreads();
#pragma unroll
    for (int off = 1; off < 256; off <<= 1) {
        int t = (tid >= off) ? sh[tid - off] : 0;
        __syncthreads();
        sh[tid] += t;
        __syncthreads();
    }
    if (i < N_NODES) g_scani[i] = sh[tid];
    if (tid == 255) g_bsum[blockIdx.x] = sh[255];
}

// fused: per-block top-prefix reduction + rowstart + dinv + cursor zero
__global__ void k_scan_add() {
    __shared__ int sh[256];
    int tid = threadIdx.x;
    int acc = 0;
    for (int j = tid; j < blockIdx.x; j += 256) acc += g_bsum[j];
    sh[tid] = acc;
    __syncthreads();
#pragma unroll
    for (int off = 128; off > 0; off >>= 1) {
        if (tid < off) sh[tid] += sh[tid + off];
        __syncthreads();
    }
    int binc = sh[0];

    int i = blockIdx.x * 256 + tid;
    if (i < N_NODES) {
        int dg = g_degi[i];
        g_rowstart[i] = g_scani[i] - dg + binc;   // exclusive prefix
        g_dinv[i] = rsqrtf((float)dg + 1.0f);
        g_cursor[i] = 0;
    }
}

__global__ void k_fill(const int* __restrict__ ei) {
    int e = blockIdx.x * blockDim.x + threadIdx.x;
    if (e < E_EDGES) {
        int s = ei[e];
        int d = ei[E_EDGES + e];
        int pos = g_rowstart[d] + atomicAdd(&g_cursor[d], 1);
        g_csr_src[pos] = s;
    }
}

// ---------------- matmul 1: t1 = dinv * (x @ W1)  (4 nodes x 16 ch, f32x2) ----------
__global__ __launch_bounds__(256) void k_mm1(const float* __restrict__ x,
                                             const float* __restrict__ W1) {
    __shared__ float Ws[IN_C * H_C];   // 32 KB
    for (int i = threadIdx.x; i < IN_C * H_C; i += 256) Ws[i] = W1[i];
    __syncthreads();

    int tid  = threadIdx.x;
    int quad = blockIdx.x * 64 + (tid >> 2);
    int nb   = quad * 4;
    if (nb >= N_NODES) return;
    int cb = (tid & 3) << 4;   // 16-channel group

    unsigned long long acc[4][8];
#pragma unroll
    for (int j = 0; j < 4; j++)
#pragma unroll
        for (int q = 0; q < 8; q++) acc[j][q] = 0ull;

    const float* xb = x + (size_t)nb * IN_C;
    for (int k4 = 0; k4 < IN_C / 4; k4++) {
        float4 xv[4];
#pragma unroll
        for (int j = 0; j < 4; j++)
            xv[j] = (nb + j < N_NODES)
                  ? *(const float4*)(xb + (size_t)j * IN_C + k4 * 4)
                  : make_float4(0.f, 0.f, 0.f, 0.f);
#pragma unroll
        for (int kk = 0; kk < 4; kk++) {
            const ulonglong2* wr = (const ulonglong2*)(&Ws[(k4 * 4 + kk) * H_C + cb]);
            ulonglong2 wv0 = wr[0], wv1 = wr[1], wv2 = wr[2], wv3 = wr[3];
            unsigned long long w[8] = {wv0.x, wv0.y, wv1.x, wv1.y,
                                       wv2.x, wv2.y, wv3.x, wv3.y};
#pragma unroll
            for (int j = 0; j < 4; j++) {
                float xs = (kk == 0) ? xv[j].x : (kk == 1) ? xv[j].y
                         : (kk == 2) ? xv[j].z : xv[j].w;
                unsigned long long xp = pack2(xs);
#pragma unroll
                for (int q = 0; q < 8; q++) fma2(acc[j][q], xp, w[q]);
            }
        }
    }

#pragma unroll
    for (int j = 0; j < 4; j++) {
        if (nb + j < N_NODES) {
            unsigned long long dv = pack2(g_dinv[nb + j]);
#pragma unroll
            for (int q = 0; q < 8; q++) mul2(acc[j][q], dv);
            ulonglong2* o = (ulonglong2*)(g_t1 + (size_t)(nb + j) * H_C + cb);
#pragma unroll
            for (int q = 0; q < 4; q++) {
                ulonglong2 v; v.x = acc[j][2*q]; v.y = acc[j][2*q+1];
                o[q] = v;
            }
        }
    }
}

// ---------------- gather ----------------
// rows of t are pre-scaled by dinv, so:
//   result[n] = (sum_{s in N(n)} t'[s] + t'[n]) * dinv[n] + bias
// warp per node; 2 channels per lane; 8-edge software pipeline, pure f32x2 adds
__global__ __launch_bounds__(256) void k_gather(int layer,
                                                const float* __restrict__ bA,
                                                const float* __restrict__ bB,
                                                float* __restrict__ outp) {
    int n = (blockIdx.x * 256 + threadIdx.x) >> 5;
    int lane = threadIdx.x & 31;
    if (n >= N_NODES) return;
    int c = lane * 2;

    const float* t = layer ? g_t2 : g_t1;

    int rs = g_rowstart[n];
    int dg = g_degi[n];
    float dd = g_dinv[n];

    unsigned long long A0 = 0, A1 = 0, A2 = 0, A3 = 0;
    unsigned long long A4 = 0, A5 = 0, A6 = 0, A7 = 0;

    int i = 0;
    for (; i + 8 <= dg; i += 8) {
        int s0 = g_csr_src[rs + i    ];
        int s1 = g_csr_src[rs + i + 1];
        int s2 = g_csr_src[rs + i + 2];
        int s3 = g_csr_src[rs + i + 3];
        int s4 = g_csr_src[rs + i + 4];
        int s5 = g_csr_src[rs + i + 5];
        int s6 = g_csr_src[rs + i + 6];
        int s7 = g_csr_src[rs + i + 7];
        unsigned long long v0 = *(const unsigned long long*)(t + (size_t)s0 * H_C + c);
        unsigned long long v1 = *(const unsigned long long*)(t + (size_t)s1 * H_C + c);
        unsigned long long v2 = *(const unsigned long long*)(t + (size_t)s2 * H_C + c);
        unsigned long long v3 = *(const unsigned long long*)(t + (size_t)s3 * H_C + c);
        unsigned long long v4 = *(const unsigned long long*)(t + (size_t)s4 * H_C + c);
        unsigned long long v5 = *(const unsigned long long*)(t + (size_t)s5 * H_C + c);
        unsigned long long v6 = *(const unsigned long long*)(t + (size_t)s6 * H_C + c);
        unsigned long long v7 = *(const unsigned long long*)(t + (size_t)s7 * H_C + c);
        add2(A0, v0); add2(A1, v1); add2(A2, v2); add2(A3, v3);
        add2(A4, v4); add2(A5, v5); add2(A6, v6); add2(A7, v7);
    }
    for (; i < dg; i++) {
        int s = g_csr_src[rs + i];
        add2(A0, *(const unsigned long long*)(t + (size_t)s * H_C + c));
    }
    // self-loop (pre-scaled row)
    add2(A0, *(const unsigned long long*)(t + (size_t)n * H_C + c));

    add2(A0, A1); add2(A2, A3); add2(A4, A5); add2(A6, A7);
    add2(A0, A2); add2(A4, A6); add2(A0, A4);

    float2 sum = *(float2*)&A0;
    float2 bias = (c < 32) ? *(const float2*)(bA + c)
                           : *(const float2*)(bB + (c - 32));
    float r0 = sum.x * dd + bias.x;
    float r1 = sum.y * dd + bias.y;

    if (layer == 0) {
        *(float2*)(g_agg1 + (size_t)n * H_C + c) =
            make_float2(fmaxf(r0, 0.f), fmaxf(r1, 0.f));
    } else {
        size_t idx = (c < 32)
            ? (size_t)n * OUT_C + c
            : (size_t)N_NODES * OUT_C + (size_t)n * OUT_C + (c - 32);
        *(float2*)(outp + idx) = make_float2(r0, r1);
    }
}

// ---------------- matmul 2: t2 = dinv * (agg1 @ [W_mu|W_logstd]) ----------
__global__ __launch_bounds__(256) void k_mm2(const float* __restrict__ Wmu,
                                             const float* __restrict__ Wls) {
    __shared__ float Ws[H_C * H_C];   // 16 KB, columns = [W_mu | W_logstd]
    for (int i = threadIdx.x; i < H_C * H_C; i += 256) {
        int k = i >> 6;
        int j = i & 63;
        Ws[i] = (j < OUT_C) ? Wmu[k * OUT_C + j] : Wls[k * OUT_C + (j - OUT_C)];
    }
    __syncthreads();

    int tid  = threadIdx.x;
    int quad = blockIdx.x * 64 + (tid >> 2);
    int nb   = quad * 4;
    if (nb >= N_NODES) return;
    int cb = (tid & 3) << 4;

    unsigned long long acc[4][8];
#pragma unroll
    for (int j = 0; j < 4; j++)
#pragma unroll
        for (int q = 0; q < 8; q++) acc[j][q] = 0ull;

    const float* hb = g_agg1 + (size_t)nb * H_C;
    for (int k4 = 0; k4 < H_C / 4; k4++) {
        float4 xv[4];
#pragma unroll
        for (int j = 0; j < 4; j++)
            xv[j] = (nb + j < N_NODES)
                  ? *(const float4*)(hb + (size_t)j * H_C + k4 * 4)
                  : make_float4(0.f, 0.f, 0.f, 0.f);
#pragma unroll
        for (int kk = 0; kk < 4; kk++) {
            const ulonglong2* wr = (const ulonglong2*)(&Ws[(k4 * 4 + kk) * H_C + cb]);
            ulonglong2 wv0 = wr[0], wv1 = wr[1], wv2 = wr[2], wv3 = wr[3];
            unsigned long long w[8] = {wv0.x, wv0.y, wv1.x, wv1.y,
                                       wv2.x, wv2.y, wv3.x, wv3.y};
#pragma unroll
            for (int j = 0; j < 4; j++) {
                float xs = (kk == 0) ? xv[j].x : (kk == 1) ? xv[j].y
                         : (kk == 2) ? xv[j].z : xv[j].w;
                unsigned long long xp = pack2(xs);
#pragma unroll
                for (int q = 0; q < 8; q++) fma2(acc[j][q], xp, w[q]);
            }
        }
    }

#pragma unroll
    for (int j = 0; j < 4; j++) {
        if (nb + j < N_NODES) {
            unsigned long long dv = pack2(g_dinv[nb + j]);
#pragma unroll
            for (int q = 0; q < 8; q++) mul2(acc[j][q], dv);
            ulonglong2* o = (ulonglong2*)(g_t2 + (size_t)(nb + j) * H_C + cb);
#pragma unroll
            for (int q = 0; q < 4; q++) {
                ulonglong2 v; v.x = acc[j][2*q]; v.y = acc[j][2*q+1];
                o[q] = v;
            }
        }
    }
}

// ---------------- launch ----------------
extern "C" void kernel_launch(void* const* d_in, const int* in_sizes, int n_in,
                              void* d_out, int out_size) {
    const float* x   = (const float*)d_in[0];
    const int*   ei  = (const int*)  d_in[1];
    const float* W1  = (const float*)d_in[2];
    const float* b1  = (const float*)d_in[3];
    const float* Wmu = (const float*)d_in[4];
    const float* bmu = (const float*)d_in[5];
    const float* Wls = (const float*)d_in[6];
    const float* bls = (const float*)d_in[7];
    float* out = (float*)d_out;

    const int TB = 256;
    const int EB = (E_EDGES + TB - 1) / TB;   // 6250

    k_init      <<<NBLK, TB>>>();
    k_degcnt    <<<EB,   TB>>>(ei);
    k_scan_block<<<NBLK, TB>>>();
    k_scan_add  <<<NBLK, TB>>>();
    k_fill      <<<EB,   TB>>>(ei);

    k_mm1<<<NBLK, TB>>>(x, W1);

    int gblocks = (N_NODES * 32 + TB - 1) / TB;   // warp per node = 12500
    k_gather<<<gblocks, TB>>>(0, b1, b1 + 32, nullptr);

    k_mm2<<<NBLK, TB>>>(Wmu, Wls);

    k_gather<<<gblocks, TB>>>(1, bmu, bls, out);
}

// round 17
// speedup vs baseline: 1.1643x; 1.0757x over previous
#include <cuda_runtime.h>

#define N_NODES 100000
#define E_EDGES 1600000
#define IN_C    128
#define H_C     64
#define OUT_C   32
#define NBLK    391          // ceil(N_NODES/256)

// ---------------- scratch (device-side access only from kernels) ----------------
__device__ __align__(16) float g_dinv[N_NODES];
__device__ int   g_degi    [N_NODES];
__device__ int   g_cursor  [N_NODES];
__device__ int   g_scani   [N_NODES];
__device__ int   g_rowstart[N_NODES];
__device__ int   g_bsum    [NBLK];
__device__ int   g_csr_src [E_EDGES];
__device__ __align__(16) float g_t1  [N_NODES * H_C];   // x@W1, then dinv-prescaled by k_scale
__device__ __align__(16) float g_agg1[N_NODES * H_C];   // relu'd layer-1 output
__device__ __align__(16) float g_t2  [N_NODES * H_C];   // dinv-prescaled h@[Wmu|Wls]

// ---------------- packed f32x2 helpers ----------------
__device__ __forceinline__ unsigned long long pack2(float x) {
    unsigned long long r;
    asm("mov.b64 %0, {%1, %1};" : "=l"(r) : "f"(x));
    return r;
}
__device__ __forceinline__ void fma2(unsigned long long& d,
                                     unsigned long long a,
                                     unsigned long long b) {
    asm("fma.rn.f32x2 %0, %1, %2, %0;" : "+l"(d) : "l"(a), "l"(b));
}
__device__ __forceinline__ void add2(unsigned long long& d,
                                     unsigned long long v) {
    asm("add.rn.f32x2 %0, %0, %1;" : "+l"(d) : "l"(v));
}
__device__ __forceinline__ void mul2(unsigned long long& d,
                                     unsigned long long v) {
    asm("mul.rn.f32x2 %0, %0, %1;" : "+l"(d) : "l"(v));
}

// ---------------- degree / CSR build ----------------
__global__ void k_degcnt(const int* __restrict__ ei) {
    int e = blockIdx.x * blockDim.x + threadIdx.x;
    if (e < E_EDGES) atomicAdd(&g_degi[ei[E_EDGES + e]], 1);
}

// block-local inclusive scan of degrees (256/block)
__global__ void k_scan_block() {
    __shared__ int sh[256];
    int tid = threadIdx.x;
    int i = blockIdx.x * 256 + tid;
    int v = (i < N_NODES) ? g_degi[i] : 0;
    sh[tid] = v;
    __syncthreads();
#pragma unroll
    for (int off = 1; off < 256; off <<= 1) {
        int t = (tid >= off) ? sh[tid - off] : 0;
        __syncthreads();
        sh[tid] += t;
        __syncthreads();
    }
    if (i < N_NODES) g_scani[i] = sh[tid];
    if (tid == 255) g_bsum[blockIdx.x] = sh[255];
}

// fused: per-block top-prefix reduction + rowstart + dinv + cursor zero
__global__ void k_scan_add() {
    __shared__ int sh[256];
    int tid = threadIdx.x;
    int acc = 0;
    for (int j = tid; j < blockIdx.x; j += 256) acc += g_bsum[j];
    sh[tid] = acc;
    __syncthreads();
#pragma unroll
    for (int off = 128; off > 0; off >>= 1) {
        if (tid < off) sh[tid] += sh[tid + off];
        __syncthreads();
    }
    int binc = sh[0];

    int i = blockIdx.x * 256 + tid;
    if (i < N_NODES) {
        int dg = g_degi[i];
        g_rowstart[i] = g_scani[i] - dg + binc;   // exclusive prefix
        g_dinv[i] = rsqrtf((float)dg + 1.0f);
        g_cursor[i] = 0;
    }
}

__global__ void k_fill(const int* __restrict__ ei) {
    int e = blockIdx.x * blockDim.x + threadIdx.x;
    if (e < E_EDGES) {
        int s = ei[e];
        int d = ei[E_EDGES + e];
        int pos = g_rowstart[d] + atomicAdd(&g_cursor[d], 1);
        g_csr_src[pos] = s;
    }
}

// ---------------- matmul 1: t1 = x @ W1  (UNSCALED; runs concurrent with CSR build) ----
__global__ __launch_bounds__(256) void k_mm1(const float* __restrict__ x,
                                             const float* __restrict__ W1) {
    __shared__ float Ws[IN_C * H_C];   // 32 KB
    for (int i = threadIdx.x; i < IN_C * H_C; i += 256) Ws[i] = W1[i];
    __syncthreads();

    int tid  = threadIdx.x;
    int quad = blockIdx.x * 64 + (tid >> 2);
    int nb   = quad * 4;
    if (nb >= N_NODES) return;
    int cb = (tid & 3) << 4;   // 16-channel group

    unsigned long long acc[4][8];
#pragma unroll
    for (int j = 0; j < 4; j++)
#pragma unroll
        for (int q = 0; q < 8; q++) acc[j][q] = 0ull;

    const float* xb = x + (size_t)nb * IN_C;
    for (int k4 = 0; k4 < IN_C / 4; k4++) {
        float4 xv[4];
#pragma unroll
        for (int j = 0; j < 4; j++)
            xv[j] = (nb + j < N_NODES)
                  ? *(const float4*)(xb + (size_t)j * IN_C + k4 * 4)
                  : make_float4(0.f, 0.f, 0.f, 0.f);
#pragma unroll
        for (int kk = 0; kk < 4; kk++) {
            const ulonglong2* wr = (const ulonglong2*)(&Ws[(k4 * 4 + kk) * H_C + cb]);
            ulonglong2 wv0 = wr[0], wv1 = wr[1], wv2 = wr[2], wv3 = wr[3];
            unsigned long long w[8] = {wv0.x, wv0.y, wv1.x, wv1.y,
                                       wv2.x, wv2.y, wv3.x, wv3.y};
#pragma unroll
            for (int j = 0; j < 4; j++) {
                float xs = (kk == 0) ? xv[j].x : (kk == 1) ? xv[j].y
                         : (kk == 2) ? xv[j].z : xv[j].w;
                unsigned long long xp = pack2(xs);
#pragma unroll
                for (int q = 0; q < 8; q++) fma2(acc[j][q], xp, w[q]);
            }
        }
    }

#pragma unroll
    for (int j = 0; j < 4; j++) {
        if (nb + j < N_NODES) {
            ulonglong2* o = (ulonglong2*)(g_t1 + (size_t)(nb + j) * H_C + cb);
#pragma unroll
            for (int q = 0; q < 4; q++) {
                ulonglong2 v; v.x = acc[j][2*q]; v.y = acc[j][2*q+1];
                o[q] = v;
            }
        }
    }
}

// ---------------- scale: t1[n] *= dinv[n]  (after mm1 ∥ CSR join) ----------------
__global__ __launch_bounds__(256) void k_scale() {
    int tid = blockIdx.x * 256 + threadIdx.x;      // N*16 float4 groups
    if (tid >= N_NODES * (H_C / 4)) return;
    int n = tid >> 4;
    float dd = g_dinv[n];
    float4* p = (float4*)g_t1 + tid;
    float4 v = *p;
    v.x *= dd; v.y *= dd; v.z *= dd; v.w *= dd;
    *p = v;
}

// ---------------- gather ----------------
// rows of t are pre-scaled by dinv, so:
//   result[n] = (sum_{s in N(n)} t'[s] + t'[n]) * dinv[n] + bias
// warp per node; 2 channels per lane; 8-edge software pipeline, pure f32x2 adds
__global__ __launch_bounds__(256) void k_gather(int layer,
                                                const float* __restrict__ bA,
                                                const float* __restrict__ bB,
                                                float* __restrict__ outp) {
    int n = (blockIdx.x * 256 + threadIdx.x) >> 5;
    int lane = threadIdx.x & 31;
    if (n >= N_NODES) return;
    int c = lane * 2;

    const float* t = layer ? g_t2 : g_t1;

    int rs = g_rowstart[n];
    int dg = g_degi[n];
    float dd = g_dinv[n];

    unsigned long long A0 = 0, A1 = 0, A2 = 0, A3 = 0;
    unsigned long long A4 = 0, A5 = 0, A6 = 0, A7 = 0;

    int i = 0;
    for (; i + 8 <= dg; i += 8) {
        int s0 = g_csr_src[rs + i    ];
        int s1 = g_csr_src[rs + i + 1];
        int s2 = g_csr_src[rs + i + 2];
        int s3 = g_csr_src[rs + i + 3];
        int s4 = g_csr_src[rs + i + 4];
        int s5 = g_csr_src[rs + i + 5];
        int s6 = g_csr_src[rs + i + 6];
        int s7 = g_csr_src[rs + i + 7];
        unsigned long long v0 = *(const unsigned long long*)(t + (size_t)s0 * H_C + c);
        unsigned long long v1 = *(const unsigned long long*)(t + (size_t)s1 * H_C + c);
        unsigned long long v2 = *(const unsigned long long*)(t + (size_t)s2 * H_C + c);
        unsigned long long v3 = *(const unsigned long long*)(t + (size_t)s3 * H_C + c);
        unsigned long long v4 = *(const unsigned long long*)(t + (size_t)s4 * H_C + c);
        unsigned long long v5 = *(const unsigned long long*)(t + (size_t)s5 * H_C + c);
        unsigned long long v6 = *(const unsigned long long*)(t + (size_t)s6 * H_C + c);
        unsigned long long v7 = *(const unsigned long long*)(t + (size_t)s7 * H_C + c);
        add2(A0, v0); add2(A1, v1); add2(A2, v2); add2(A3, v3);
        add2(A4, v4); add2(A5, v5); add2(A6, v6); add2(A7, v7);
    }
    for (; i < dg; i++) {
        int s = g_csr_src[rs + i];
        add2(A0, *(const unsigned long long*)(t + (size_t)s * H_C + c));
    }
    // self-loop (pre-scaled row)
    add2(A0, *(const unsigned long long*)(t + (size_t)n * H_C + c));

    add2(A0, A1); add2(A2, A3); add2(A4, A5); add2(A6, A7);
    add2(A0, A2); add2(A4, A6); add2(A0, A4);

    float2 sum = *(float2*)&A0;
    float2 bias = (c < 32) ? *(const float2*)(bA + c)
                           : *(const float2*)(bB + (c - 32));
    float r0 = sum.x * dd + bias.x;
    float r1 = sum.y * dd + bias.y;

    if (layer == 0) {
        *(float2*)(g_agg1 + (size_t)n * H_C + c) =
            make_float2(fmaxf(r0, 0.f), fmaxf(r1, 0.f));
    } else {
        size_t idx = (c < 32)
            ? (size_t)n * OUT_C + c
            : (size_t)N_NODES * OUT_C + (size_t)n * OUT_C + (c - 32);
        *(float2*)(outp + idx) = make_float2(r0, r1);
    }
}

// ---------------- matmul 2: t2 = dinv * (agg1 @ [W_mu|W_logstd]) ----------
__global__ __launch_bounds__(256) void k_mm2(const float* __restrict__ Wmu,
                                             const float* __restrict__ Wls) {
    __shared__ float Ws[H_C * H_C];   // 16 KB, columns = [W_mu | W_logstd]
    for (int i = threadIdx.x; i < H_C * H_C; i += 256) {
        int k = i >> 6;
        int j = i & 63;
        Ws[i] = (j < OUT_C) ? Wmu[k * OUT_C + j] : Wls[k * OUT_C + (j - OUT_C)];
    }
    __syncthreads();

    int tid  = threadIdx.x;
    int quad = blockIdx.x * 64 + (tid >> 2);
    int nb   = quad * 4;
    if (nb >= N_NODES) return;
    int cb = (tid & 3) << 4;

    unsigned long long acc[4][8];
#pragma unroll
    for (int j = 0; j < 4; j++)
#pragma unroll
        for (int q = 0; q < 8; q++) acc[j][q] = 0ull;

    const float* hb = g_agg1 + (size_t)nb * H_C;
    for (int k4 = 0; k4 < H_C / 4; k4++) {
        float4 xv[4];
#pragma unroll
        for (int j = 0; j < 4; j++)
            xv[j] = (nb + j < N_NODES)
                  ? *(const float4*)(hb + (size_t)j * H_C + k4 * 4)
                  : make_float4(0.f, 0.f, 0.f, 0.f);
#pragma unroll
        for (int kk = 0; kk < 4; kk++) {
            const ulonglong2* wr = (const ulonglong2*)(&Ws[(k4 * 4 + kk) * H_C + cb]);
            ulonglong2 wv0 = wr[0], wv1 = wr[1], wv2 = wr[2], wv3 = wr[3];
            unsigned long long w[8] = {wv0.x, wv0.y, wv1.x, wv1.y,
                                       wv2.x, wv2.y, wv3.x, wv3.y};
#pragma unroll
            for (int j = 0; j < 4; j++) {
                float xs = (kk == 0) ? xv[j].x : (kk == 1) ? xv[j].y
                         : (kk == 2) ? xv[j].z : xv[j].w;
                unsigned long long xp = pack2(xs);
#pragma unroll
                for (int q = 0; q < 8; q++) fma2(acc[j][q], xp, w[q]);
            }
        }
    }

#pragma unroll
    for (int j = 0; j < 4; j++) {
        if (nb + j < N_NODES) {
            unsigned long long dv = pack2(g_dinv[nb + j]);
#pragma unroll
            for (int q = 0; q < 8; q++) mul2(acc[j][q], dv);
            ulonglong2* o = (ulonglong2*)(g_t2 + (size_t)(nb + j) * H_C + cb);
#pragma unroll
            for (int q = 0; q < 4; q++) {
                ulonglong2 v; v.x = acc[j][2*q]; v.y = acc[j][2*q+1];
                o[q] = v;
            }
        }
    }
}

// ---------------- launch ----------------
extern "C" void kernel_launch(void* const* d_in, const int* in_sizes, int n_in,
                              void* d_out, int out_size) {
    const float* x   = (const float*)d_in[0];
    const int*   ei  = (const int*)  d_in[1];
    const float* W1  = (const float*)d_in[2];
    const float* b1  = (const float*)d_in[3];
    const float* Wmu = (const float*)d_in[4];
    const float* bmu = (const float*)d_in[5];
    const float* Wls = (const float*)d_in[6];
    const float* bls = (const float*)d_in[7];
    float* out = (float*)d_out;

    const int TB = 256;
    const int EB = (E_EDGES + TB - 1) / TB;   // 6250

    // fork stream + events (created per call; never destroyed — destroying a
    // capture-participating stream would invalidate graph capture)
    cudaStream_t s2;
    cudaStreamCreateWithFlags(&s2, cudaStreamNonBlocking);
    cudaEvent_t e_fork, e_mm1;
    cudaEventCreateWithFlags(&e_fork, cudaEventDisableTiming);
    cudaEventCreateWithFlags(&e_mm1,  cudaEventDisableTiming);

    // zero degree counters via memset node
    void* degi_ptr = nullptr;
    cudaGetSymbolAddress(&degi_ptr, g_degi);
    cudaMemsetAsync(degi_ptr, 0, N_NODES * sizeof(int), 0);

    // fork: mm1 (x @ W1, unscaled) runs concurrently with the CSR build
    cudaEventRecord(e_fork, 0);
    cudaStreamWaitEvent(s2, e_fork, 0);
    k_mm1<<<NBLK, TB, 0, s2>>>(x, W1);
    cudaEventRecord(e_mm1, s2);

    // CSR build on origin stream
    k_degcnt    <<<EB,   TB>>>(ei);
    k_scan_block<<<NBLK, TB>>>();
    k_scan_add  <<<NBLK, TB>>>();
    k_fill      <<<EB,   TB>>>(ei);

    // join: need t1 (s2) and dinv (origin) before scaling
    cudaStreamWaitEvent(0, e_mm1, 0);
    int sblocks = (N_NODES * (H_C / 4) + TB - 1) / TB;   // 6250
    k_scale<<<sblocks, TB>>>();

    int gblocks = (N_NODES * 32 + TB - 1) / TB;   // warp per node = 12500
    k_gather<<<gblocks, TB>>>(0, b1, b1 + 32, nullptr);

    k_mm2<<<NBLK, TB>>>(Wmu, Wls);

    k_gather<<<gblocks, TB>>>(1, bmu, bls, out);
}